// round 12
// baseline (speedup 1.0000x reference)
#include <cuda_runtime.h>
#include <math.h>

// Problem constants (hardcoded in reference)
#define B 32
#define D 128
#define K 512
#define C 10
#define KH 256            // half-K
#define NT 1024
#define NPROD 20          // (c, half) producers
#define NCONS 64          // (b, half) consumers

// Cross-CTA state
__device__ float g_fac2[C][K];
__device__ float g_h[B * C];                     // 2-way atomicAdd merge (init 0)
__device__ __align__(16) int g_pflag[NPROD];     // producer release-flags
__device__ int g_rowcnt[B];                      // halves arrived per row
__device__ int g_done = 0;                       // winners done (target B)

__device__ __forceinline__ void st_release_gpu(int* p, int v) {
    asm volatile("st.release.gpu.global.s32 [%0], %1;" :: "l"(p), "r"(v) : "memory");
}
__device__ __forceinline__ int4 ld_volatile_v4(const int4* p) {
    int4 v;
    asm volatile("ld.volatile.global.v4.s32 {%0,%1,%2,%3}, [%4];"
                 : "=r"(v.x), "=r"(v.y), "=r"(v.z), "=r"(v.w) : "l"(p) : "memory");
    return v;
}
__device__ __forceinline__ float ld_acquire_f32(const float* p) {
    float v;
    asm volatile("ld.acquire.gpu.global.f32 %0, [%1];" : "=f"(v) : "l"(p) : "memory");
    return v;
}
__device__ __forceinline__ void fence_acq_rel_gpu() {
    asm volatile("fence.acq_rel.gpu;" ::: "memory");
}

// 84 CTAs x 1024 threads (single wave):
//   CTA 0..63  : consumer (b = blk>>1, half = blk&1) — streams 128 KB of U
//   CTA 64..83 : producer (c = pid>>1, half = pid&1) — streams 128 KB of V
__global__ __launch_bounds__(NT, 1) void fused_kernel(
    const float* __restrict__ x,
    const float* __restrict__ mu,
    const float* __restrict__ U,
    const float* __restrict__ V,
    float* __restrict__ out) {
    __shared__ float sx[D];
    __shared__ float part[16][KH];   // 16 d-groups x 256 (16 KB)
    __shared__ float f1s[KH];
    __shared__ int   swin;

    const int t    = threadIdx.x;
    const int w    = t >> 5;
    const int lane = t & 31;
    const int g    = t >> 6;         // d-group 0..15 (8 d-rows each)
    const int tt   = t & 63;         // float4 col within the half

    const bool producer = (blockIdx.x >= NCONS);
    const int  pid  = producer ? (blockIdx.x - NCONS) : blockIdx.x;
    const int  row  = pid >> 1;      // b or c
    const int  half = pid & 1;

    const float* src = producer ? (mu + row * D) : (x + row * D);
    const float* Wg  = (producer ? V : U) + half * KH + g * 8 * K;

    if (t < D) sx[t] = src[t];

    // front-batched: all 8 LDG.128 in flight before the smem-operand wait
    float4 wv[8];
#pragma unroll
    for (int i = 0; i < 8; i++)
        wv[i] = reinterpret_cast<const float4*>(Wg + i * K)[tt];
    __syncthreads();

    float4 acc = make_float4(0.f, 0.f, 0.f, 0.f);
    const float* sg = sx + g * 8;
#pragma unroll
    for (int i = 0; i < 8; i++) {
        const float sv = sg[i];
        acc.x = fmaf(sv, wv[i].x, acc.x);
        acc.y = fmaf(sv, wv[i].y, acc.y);
        acc.z = fmaf(sv, wv[i].z, acc.z);
        acc.w = fmaf(sv, wv[i].w, acc.w);
    }
    reinterpret_cast<float4*>(&part[g][tt * 4])[0] = acc;
    __syncthreads();

    if (producer) {
        // reduce 16 d-partials, publish fac2 half-row, release own flag
        if (t < 64) {
            float4 r = make_float4(0.f, 0.f, 0.f, 0.f);
#pragma unroll
            for (int gg = 0; gg < 16; gg++) {
                float4 a = reinterpret_cast<const float4*>(&part[gg][t * 4])[0];
                r.x += a.x; r.y += a.y; r.z += a.z; r.w += a.w;
            }
            reinterpret_cast<float4*>(&g_fac2[row][half * KH])[t] = r;
        }
        __syncthreads();                 // stores happen-before flag
        if (t == 0) st_release_gpu(&g_pflag[pid], 1);
        return;
    }

    // ---------------- consumer ----------------
    // fold d-group partials while thread 0 polls the 20 flags
    if (t == 0) {
        const int4* fp = reinterpret_cast<const int4*>(g_pflag);
        for (;;) {
            int s = 0;
#pragma unroll
            for (int j = 0; j < NPROD / 4; j++) {
                int4 f = ld_volatile_v4(fp + j);
                s += f.x + f.y + f.z + f.w;
            }
            if (s == NPROD) break;
        }
        fence_acq_rel_gpu();
    }
    if (t >= 512 && t < 512 + KH) {      // disjoint warps fold while warp 0 polls
        const int k = t - 512;
        float f = part[0][k];
#pragma unroll
        for (int gg = 1; gg < 16; gg++) f += part[gg][k];
        f1s[k] = f;
    }
    __syncthreads();                     // f1s ready AND fac2 visible

    // one warp per class: dot(f1s, fac2[c, half]) over 256 (2 float4/lane)
    if (w < C) {
        const float4* fa = reinterpret_cast<const float4*>(f1s);
        const float4* fb = reinterpret_cast<const float4*>(&g_fac2[w][half * KH]);
        float p = 0.f;
#pragma unroll
        for (int j = 0; j < 2; j++) {
            const int i4 = lane + j * 32;
            float4 a = fa[i4];
            float4 b2 = fb[i4];
            p += a.x * b2.x + a.y * b2.y + a.z * b2.z + a.w * b2.w;
        }
#pragma unroll
        for (int o = 16; o > 0; o >>= 1)
            p += __shfl_xor_sync(0xffffffffu, p, o);
        // 2-way commutative fp32 add: bitwise deterministic regardless of order
        if (lane == 0) atomicAdd(&g_h[row * C + w], p);
    }
    __syncthreads();                     // all 10 atomicAdds issued
    if (t == 0) {
        __threadfence();                 // publish adds before counter
        swin = (atomicAdd(&g_rowcnt[row], 1) == 1);
    }
    __syncthreads();
    if (!swin) return;

    // ---- winner: parallel log_softmax for row b (lane c owns class c) ----
    if (w == 0) {
        fence_acq_rel_gpu();             // acquire partner's adds (all lanes)
        float h = (lane < C) ? ld_acquire_f32(&g_h[row * C + lane]) : -INFINITY;
        float m = h;
#pragma unroll
        for (int o = 8; o > 0; o >>= 1)
            m = fmaxf(m, __shfl_xor_sync(0xffffffffu, m, o));
        m = __shfl_sync(0xffffffffu, m, 0);
        float e = (lane < C) ? __expf(h - m) : 0.f;   // MUFU.EX2
        float se = e;
#pragma unroll
        for (int o = 8; o > 0; o >>= 1)
            se += __shfl_xor_sync(0xffffffffu, se, o);
        se = __shfl_sync(0xffffffffu, se, 0);
        const float lse = m + __logf(se);             // MUFU.LG2
        if (lane < C) {
            out[row * C + lane] = h - lse;
            g_h[row * C + lane] = 0.f;   // reset for next graph replay
        }
        if (lane == 0) {
            g_rowcnt[row] = 0;
            // last winner resets producer flags
            if (atomicAdd(&g_done, 1) == B - 1) {
#pragma unroll
                for (int j = 0; j < NPROD; j++) g_pflag[j] = 0;
                g_done = 0;
            }
        }
    }
}

extern "C" void kernel_launch(void* const* d_in, const int* in_sizes, int n_in,
                              void* d_out, int out_size) {
    const float* x  = (const float*)d_in[0];  // [32, 128]
    const float* mu = (const float*)d_in[1];  // [10, 128]
    const float* U  = (const float*)d_in[2];  // [128, 512]
    const float* V  = (const float*)d_in[3];  // [128, 512]
    float* out = (float*)d_out;               // [32, 10]

    fused_kernel<<<NCONS + NPROD, NT>>>(x, mu, U, V, out);
}